// round 14
// baseline (speedup 1.0000x reference)
#include <cuda_runtime.h>
#include <cuda_bf16.h>
#include <math.h>
#include <cstdint>

// Problem constants
#define SQ    2048
#define DM    1024
#define NH    16
#define DKH   64
#define NB    2
#define NTOK  (NB*SQ)   // 4096
#define BH    (NB*NH)   // 32

// ---------------------------------------------------------------------------
// Scratch (no cudaMalloc allowed)
// ---------------------------------------------------------------------------
__device__ uint32_t g_Qhi[(size_t)BH*SQ*32];     // [B,H,S,dk-pairs]
__device__ uint32_t g_Qlo[(size_t)BH*SQ*32];
// K combined: [B,H,S][4 t][4 tig][kh0,kh1,kl0,kl1]  (64 u32 per key)
__device__ uint32_t g_Kc [(size_t)BH*SQ*64];
// V combined: [B,H,dk][32 kt][4 t][4 tig][vh0,vh1,vl0,vl1] (2048 u32 per dk)
__device__ uint32_t g_Vc [(size_t)BH*DKH*32*64];
__device__ float g_X  [(size_t)NTOK*DM];         // attn out, tf32 + k-interleaved
// pre-rounded + k-interleaved fp32(tf32) inputs / weights
__device__ float g_qc [(size_t)NTOK*DM];
__device__ float g_kc [(size_t)NTOK*DM];
__device__ float g_vc [(size_t)NTOK*DM];
__device__ float g_Wqc[(size_t)DM*DM];
__device__ float g_Wkc[(size_t)DM*DM];
__device__ float g_Wvc[(size_t)DM*DM];
__device__ float g_Woc[(size_t)DM*DM];

// ---------------------------------------------------------------------------
// Helpers
// ---------------------------------------------------------------------------
__device__ __forceinline__ uint32_t f2tf32(float f) {
    uint32_t r;
    asm("cvt.rna.tf32.f32 %0, %1;" : "=r"(r) : "f"(f));
    return r;
}
__device__ __forceinline__ float tf32hi(float f) {
    return __uint_as_float(f2tf32(f));
}
__device__ __forceinline__ float ex2(float x) {
    float y;
    asm("ex2.approx.f32 %0, %1;" : "=f"(y) : "f"(x));
    return y;
}
// pack two floats as bf16x2: low half = e, high half = o
__device__ __forceinline__ uint32_t pack_bf16(float e, float o) {
    uint32_t r;
    asm("cvt.rn.bf16x2.f32 %0, %1, %2;" : "=r"(r) : "f"(o), "f"(e));
    return r;
}
__device__ __forceinline__ float blo_f(uint32_t p) { return __uint_as_float(p << 16); }
__device__ __forceinline__ float bhi_f(uint32_t p) { return __uint_as_float(p & 0xffff0000u); }

__device__ __forceinline__ void mma_tf32(float c[4], const uint32_t a[4],
                                         const uint32_t b0, const uint32_t b1) {
    asm volatile(
        "mma.sync.aligned.m16n8k8.row.col.f32.tf32.tf32.f32 "
        "{%0,%1,%2,%3}, {%4,%5,%6,%7}, {%8,%9}, {%0,%1,%2,%3};"
        : "+f"(c[0]), "+f"(c[1]), "+f"(c[2]), "+f"(c[3])
        : "r"(a[0]), "r"(a[1]), "r"(a[2]), "r"(a[3]),
          "r"(b0), "r"(b1));
}
__device__ __forceinline__ void mma_bf16(float c[4], const uint32_t a[4],
                                         const uint32_t b0, const uint32_t b1) {
    asm volatile(
        "mma.sync.aligned.m16n8k16.row.col.f32.bf16.bf16.f32 "
        "{%0,%1,%2,%3}, {%4,%5,%6,%7}, {%8,%9}, {%0,%1,%2,%3};"
        : "+f"(c[0]), "+f"(c[1]), "+f"(c[2]), "+f"(c[3])
        : "r"(a[0]), "r"(a[1]), "r"(a[2]), "r"(a[3]),
          "r"(b0), "r"(b1));
}
__device__ __forceinline__ void cp16(uint32_t saddr, const void* g) {
    asm volatile("cp.async.cg.shared.global [%0], [%1], 16;"
                 :: "r"(saddr), "l"(g) : "memory");
}
#define CP_COMMIT() asm volatile("cp.async.commit_group;" ::: "memory")

__device__ __forceinline__ uint32_t smem_u32(const void* p) {
    uint32_t a;
    asm("{ .reg .u64 t; cvta.to.shared.u64 t, %1; cvt.u32.u64 %0, t; }"
        : "=r"(a) : "l"(p));
    return a;
}

// ---------------------------------------------------------------------------
// Merged tf32 pre-round + k-interleave pass.
// Storage order within each 8-col group: [k0,k4,k1,k5,k2,k6,k3,k7]
// (s(k) = (k&3)*2 + (k>>2)), so fragment pairs (k, k+4) are adjacent.
// ---------------------------------------------------------------------------
struct CvtJobs {
    const float4* src[7];
    float4*       dst[7];
    int           n8[7];   // number of 8-float groups
};

__global__ __launch_bounds__(256)
void cvt_tf32_k(CvtJobs jobs)
{
    const int a = blockIdx.y;
    const int i = blockIdx.x*blockDim.x + threadIdx.x;
    if (i < jobs.n8[a]) {
        float4 lo = jobs.src[a][2*i];
        float4 hi = jobs.src[a][2*i+1];
        float4 d0, d1;
        d0.x = tf32hi(lo.x); d0.y = tf32hi(hi.x);
        d0.z = tf32hi(lo.y); d0.w = tf32hi(hi.y);
        d1.x = tf32hi(lo.z); d1.y = tf32hi(hi.z);
        d1.z = tf32hi(lo.w); d1.w = tf32hi(hi.w);
        jobs.dst[a][2*i]   = d0;
        jobs.dst[a][2*i+1] = d1;
    }
}

// ---------------------------------------------------------------------------
// tf32 mma.sync GEMM, 2-stage cp.async pipeline, k-interleaved inputs,
// LDS.64 fragment loads. Merged jobs (grid.z).
// mode 0: C row-major fp32 [M,N]  (final output)
// mode 1: bf16 hi/lo packed dk-pairs -> C,C2 u32 [B,H,S,32]   (Q)
// mode 4: K combined-interleaved u32 [B,H,S,64]               (K)
// mode 5: V combined-interleaved u16 writes into u32 [B,H,dk,2048] (V)
// ---------------------------------------------------------------------------
#define BK 32
#define KP 40                          // row stride (u32), ≡8 mod 32
#define TILE_WORDS (128*KP)            // 5120
#define STAGE_W    (2*TILE_WORDS)      // 10240
#define GEMM_SMEM  (2*STAGE_W*4)       // 81920 B
#define GEMM_NT    (DM/BK)             // 32

struct GemmJobs {
    const float* A[3];
    const float* W[3];
    const float* bias[3];
    void*        C[3];
    void*        C2[3];
    int          mode[3];
};

__global__ __launch_bounds__(256, 2)
void gemm_tf32(GemmJobs jobs)
{
    extern __shared__ uint32_t sh[];
    const uint32_t smem0 = smem_u32(sh);

    const int z = blockIdx.z;
    const float* __restrict__ A    = jobs.A[z];
    const float* __restrict__ W    = jobs.W[z];
    const float* __restrict__ bias = jobs.bias[z];
    void* C  = jobs.C[z];
    void* C2 = jobs.C2[z];
    const int mode = jobs.mode[z];

    const int tid    = threadIdx.x;
    const int wid    = tid >> 5;
    const int lane   = tid & 31;
    const int gid    = lane >> 2;
    const int tig    = lane & 3;
    const int warp_m = (wid >> 2) * 64;
    const int warp_n = (wid & 3) * 32;
    const int bx     = blockIdx.x;
    const int by     = blockIdx.y;

    const float* Ab = A + (size_t)(by*128)*DM;
    const float* Wb = W + (size_t)(bx*128)*DM;

    auto prefetch = [&](int kt) {
        if (kt < GEMM_NT) {
            const uint32_t base = smem0 + (kt & 1)*(STAGE_W*4);
            #pragma unroll
            for (int t = 0; t < 8; t++) {
                int chunk = tid + t*256;            // 0..2047
                int arr   = chunk >> 10;            // 0=A, 1=B
                int w     = chunk & 1023;
                int row   = w >> 3;
                int kc4   = (w & 7) * 4;
                uint32_t so = (uint32_t)((arr*TILE_WORDS + row*KP + kc4)*4);
                const float* src = (arr ? Wb : Ab) + (size_t)row*DM + kt*BK + kc4;
                cp16(base + so, src);
            }
        }
        CP_COMMIT();
    };

    float acc[4][4][4];
    #pragma unroll
    for (int i = 0; i < 4; i++)
        #pragma unroll
        for (int j = 0; j < 4; j++)
            #pragma unroll
            for (int r = 0; r < 4; r++) acc[i][j][r] = 0.0f;

    prefetch(0);

    for (int kt = 0; kt < GEMM_NT; kt++) {
        prefetch(kt + 1);   // stage (kt+1)&1 freed by trailing barrier of prev iter
        asm volatile("cp.async.wait_group 1;" ::: "memory");
        __syncthreads();

        const uint32_t* a = sh + (kt & 1)*STAGE_W;
        const uint32_t* b = a + TILE_WORDS;

        #pragma unroll
        for (int ks = 0; ks < BK; ks += 8) {
            uint32_t af[4][4], bf[4][2];
            #pragma unroll
            for (int i = 0; i < 4; i++) {
                int r0 = warp_m + i*16 + gid;
                uint2 A0 = *(const uint2*)&a[ r0    *KP + ks + 2*tig];
                uint2 A1 = *(const uint2*)&a[(r0+8) *KP + ks + 2*tig];
                af[i][0] = A0.x; af[i][1] = A1.x;
                af[i][2] = A0.y; af[i][3] = A1.y;
            }
            #pragma unroll
            for (int j = 0; j < 4; j++) {
                int n = warp_n + j*8 + gid;
                uint2 B0 = *(const uint2*)&b[n*KP + ks + 2*tig];
                bf[j][0] = B0.x; bf[j][1] = B0.y;
            }
            #pragma unroll
            for (int i = 0; i < 4; i++)
                #pragma unroll
                for (int j = 0; j < 4; j++)
                    mma_tf32(acc[i][j], af[i], bf[j][0], bf[j][1]);
        }
        __syncthreads();   // free this stage for prefetch(kt+2)
    }

    #pragma unroll
    for (int i = 0; i < 4; i++) {
        #pragma unroll
        for (int j = 0; j < 4; j++) {
            int row0 = by*128 + warp_m + i*16 + gid;
            int row1 = row0 + 8;
            int col  = bx*128 + warp_n + j*8 + tig*2;
            float bx0 = bias[col], bx1 = bias[col+1];
            float v00 = acc[i][j][0] + bx0, v01 = acc[i][j][1] + bx1;
            float v10 = acc[i][j][2] + bx0, v11 = acc[i][j][3] + bx1;
            if (mode == 0) {
                float* Cf = (float*)C;
                *(float2*)(Cf + (size_t)row0*DM + col) = make_float2(v00, v01);
                *(float2*)(Cf + (size_t)row1*DM + col) = make_float2(v10, v11);
            } else if (mode == 1) {
                // Q: bf16 hi/lo packed dk-pairs [B,H,S,32]
                int h = col >> 6, dkp = (col & 63) >> 1;
                int b0r = row0 >> 11, s0 = row0 & (SQ-1);
                int b1r = row1 >> 11, s1 = row1 & (SQ-1);
                size_t o0 = ((size_t)(b0r*NH + h)*SQ + s0)*32 + dkp;
                size_t o1 = ((size_t)(b1r*NH + h)*SQ + s1)*32 + dkp;
                uint32_t h0 = pack_bf16(v00, v01);
                uint32_t h1 = pack_bf16(v10, v11);
                ((uint32_t*)C)[o0] = h0;
                ((uint32_t*)C)[o1] = h1;
                ((uint32_t*)C2)[o0] = pack_bf16(v00 - blo_f(h0), v01 - bhi_f(h0));
                ((uint32_t*)C2)[o1] = pack_bf16(v10 - blo_f(h1), v11 - bhi_f(h1));
            } else if (mode == 4) {
                // K combined: [B,H,S][t*16 + tig*4 + {h0,h1,l0,l1}]
                int h = col >> 6, dkp = (col & 63) >> 1;
                int t = dkp >> 3, p = dkp & 7;
                int tg = p & 3, sl = p >> 2;
                int b0r = row0 >> 11, s0 = row0 & (SQ-1);
                int b1r = row1 >> 11, s1 = row1 & (SQ-1);
                size_t o0 = ((size_t)(b0r*NH + h)*SQ + s0)*64 + t*16 + tg*4 + sl;
                size_t o1 = ((size_t)(b1r*NH + h)*SQ + s1)*64 + t*16 + tg*4 + sl;
                uint32_t h0 = pack_bf16(v00, v01);
                uint32_t h1 = pack_bf16(v10, v11);
                uint32_t* Kc = (uint32_t*)C;
                Kc[o0]     = h0;
                Kc[o0 + 2] = pack_bf16(v00 - blo_f(h0), v01 - bhi_f(h0));
                Kc[o1]     = h1;
                Kc[o1 + 2] = pack_bf16(v10 - blo_f(h1), v11 - bhi_f(h1));
            } else {
                // mode 5: V combined, u16 scatter into [B,H,dk][kt*64 + ...]
                unsigned short* Vc16 = (unsigned short*)C;
                #pragma unroll
                for (int u = 0; u < 4; u++) {
                    int s  = (u < 2) ? row0 : row1;
                    int dk = col + (u & 1);
                    float f = (u == 0) ? v00 : (u == 1) ? v01 : (u == 2) ? v10 : v11;
                    int br = s >> 11; int ss = s & (SQ-1);
                    int h  = dk >> 6; int dkl = dk & 63;
                    int kt = ss >> 6, q = ss & 63;
                    int pp = q >> 1, par = q & 1;
                    int t = pp >> 3, r = pp & 7;
                    int tg = r & 3, sl = r >> 2;
                    size_t u32idx = (((size_t)(br*NH + h)*DKH + dkl)*32 + kt)*64
                                  + t*16 + tg*4 + sl;
                    uint32_t ph = pack_bf16(f, 0.0f);
                    float fh = blo_f(ph);
                    uint32_t pl = pack_bf16(f - fh, 0.0f);
                    Vc16[u32idx*2 + par]       = (unsigned short)(ph & 0xffff);
                    Vc16[(u32idx + 2)*2 + par] = (unsigned short)(pl & 0xffff);
                }
            }
        }
    }
}

// ---------------------------------------------------------------------------
// bf16 tensor-core causal flash attention (3-term compensated splits).
// K/V smem: combined-interleaved rows, stride 80 u32 (≡16 mod 32):
// one LDS.128 yields {h0,h1,l0,l1} per (j,t) fragment group.
// ---------------------------------------------------------------------------
#define AT_RS       80                        // row stride (u32)
#define KV_ROW_W    64                        // payload u32 per row
#define ARR_W       (64*AT_RS)                // 5120 u32 per array
#define STAGE_WORDS (2*ARR_W)                 // 10240 u32 (K + V)
#define ATTN_SMEM   (2*STAGE_WORDS*4)         // 81920 B
#define COEF 0.18033688f                      // 0.125 * log2(e)

__global__ __launch_bounds__(256, 1)
void attn_tc(const uint32_t* __restrict__ Qhi, const uint32_t* __restrict__ Qlo,
             const uint32_t* __restrict__ Kc,  const uint32_t* __restrict__ Vc,
             float* __restrict__ X)
{
    extern __shared__ uint32_t sh[];
    const uint32_t smem0 = smem_u32(sh);

    const int qt   = (int)gridDim.x - 1 - (int)blockIdx.x;  // heavy tiles first
    const int bh   = blockIdx.y;
    const int tid  = threadIdx.x;
    const int wid  = tid >> 5;
    const int lane = tid & 31;
    const int gid  = lane >> 2;
    const int tig  = lane & 3;

    const int row0 = qt*128 + wid*16 + gid;
    const int row1 = row0 + 8;

    // Q fragments (pre-split bf16 pairs) in registers
    uint32_t qh[4][4], ql[4][4];
    {
        const uint32_t* q0h = Qhi + ((size_t)bh*SQ + row0)*32;
        const uint32_t* q1h = Qhi + ((size_t)bh*SQ + row1)*32;
        const uint32_t* q0l = Qlo + ((size_t)bh*SQ + row0)*32;
        const uint32_t* q1l = Qlo + ((size_t)bh*SQ + row1)*32;
        #pragma unroll
        for (int t = 0; t < 4; t++) {
            qh[t][0] = q0h[8*t + tig];     qh[t][1] = q1h[8*t + tig];
            qh[t][2] = q0h[8*t + tig + 4]; qh[t][3] = q1h[8*t + tig + 4];
            ql[t][0] = q0l[8*t + tig];     ql[t][1] = q1l[8*t + tig];
            ql[t][2] = q0l[8*t + tig + 4]; ql[t][3] = q1l[8*t + tig + 4];
        }
    }

    float o[8][4];
    #pragma unroll
    for (int j = 0; j < 8; j++)
        #pragma unroll
        for (int r = 0; r < 4; r++) o[j][r] = 0.0f;
    float m0 = -INFINITY, m1 = -INFINITY, l0 = 0.0f, l1 = 0.0f;

    const uint32_t* KcG = Kc + (size_t)bh*SQ*64;
    const uint32_t* VcG = Vc + (size_t)bh*DKH*32*64;

    auto prefetch = [&](int kt, int st) {
        const uint32_t base = smem0 + st*(STAGE_WORDS*4);
        #pragma unroll
        for (int t = 0; t < 8; t++) {
            int chunk = tid + t*256;         // 0..2047
            int arr   = chunk >> 10;         // 0=K, 1=V
            int w     = chunk & 1023;
            int row   = w >> 4;              // 0..63
            int ch    = (w & 15) * 4;        // u32 offset within payload
            uint32_t saddr = base + (uint32_t)((arr*ARR_W + row*AT_RS + ch)*4);
            const uint32_t* src = arr
                ? VcG + (size_t)row*2048 + kt*64 + ch
                : KcG + (size_t)(kt*64 + row)*64 + ch;
            cp16(saddr, src);
        }
        CP_COMMIT();
    };

    const int ktmax = 2*qt + 1;
    prefetch(0, 0);

    for (int kt = 0; kt <= ktmax; kt++) {
        const int st = kt & 1;
        asm volatile("cp.async.wait_group 0;" ::: "memory");
        __syncthreads();
        if (kt < ktmax) prefetch(kt + 1, st ^ 1);

        const uint32_t* sK = sh + st*STAGE_WORDS;
        const uint32_t* sV = sK + ARR_W;

        // S = Q K^T  (3-term bf16)
        float sc[8][4];
        #pragma unroll
        for (int j = 0; j < 8; j++)
            #pragma unroll
            for (int r = 0; r < 4; r++) sc[j][r] = 0.0f;

        #pragma unroll
        for (int j = 0; j < 8; j++) {
            const int nrow = (8*j + gid)*AT_RS + tig*4;
            #pragma unroll
            for (int t = 0; t < 4; t++) {
                uint4 kc = *(const uint4*)&sK[nrow + t*16];
                mma_bf16(sc[j], qh[t], kc.x, kc.y);
                mma_bf16(sc[j], qh[t], kc.z, kc.w);
                mma_bf16(sc[j], ql[t], kc.x, kc.y);
            }
        }

        // Causal mask
        if (kt*64 + 63 > row0) {
            #pragma unroll
            for (int j = 0; j < 8; j++) {
                int col = kt*64 + 8*j + 2*tig;
                if (col     > row0) sc[j][0] = -1e30f;
                if (col + 1 > row0) sc[j][1] = -1e30f;
                if (col     > row1) sc[j][2] = -1e30f;
                if (col + 1 > row1) sc[j][3] = -1e30f;
            }
        }

        // Online softmax
        float mx0 = -INFINITY, mx1 = -INFINITY;
        #pragma unroll
        for (int j = 0; j < 8; j++) {
            mx0 = fmaxf(mx0, fmaxf(sc[j][0], sc[j][1]));
            mx1 = fmaxf(mx1, fmaxf(sc[j][2], sc[j][3]));
        }
        #pragma unroll
        for (int off = 1; off <= 2; off <<= 1) {
            mx0 = fmaxf(mx0, __shfl_xor_sync(0xffffffffu, mx0, off));
            mx1 = fmaxf(mx1, __shfl_xor_sync(0xffffffffu, mx1, off));
        }
        float mn0 = fmaxf(m0, mx0), mn1 = fmaxf(m1, mx1);
        float a0 = ex2((m0 - mn0)*COEF), a1 = ex2((m1 - mn1)*COEF);
        m0 = mn0; m1 = mn1;

        float ls0 = 0.0f, ls1 = 0.0f;
        #pragma unroll
        for (int j = 0; j < 8; j++) {
            sc[j][0] = ex2((sc[j][0] - m0)*COEF);
            sc[j][1] = ex2((sc[j][1] - m0)*COEF);
            sc[j][2] = ex2((sc[j][2] - m1)*COEF);
            sc[j][3] = ex2((sc[j][3] - m1)*COEF);
            ls0 += sc[j][0] + sc[j][1];
            ls1 += sc[j][2] + sc[j][3];
        }
        #pragma unroll
        for (int off = 1; off <= 2; off <<= 1) {
            ls0 += __shfl_xor_sync(0xffffffffu, ls0, off);
            ls1 += __shfl_xor_sync(0xffffffffu, ls1, off);
        }
        l0 = l0*a0 + ls0;
        l1 = l1*a1 + ls1;
        #pragma unroll
        for (int j = 0; j < 8; j++) {
            o[j][0] *= a0; o[j][1] *= a0;
            o[j][2] *= a1; o[j][3] *= a1;
        }

        // P: accumulator pairs -> k16 A fragments via bf16x2 packing (no shfl)
        uint32_t ph[4][4], pl[4][4];
        #pragma unroll
        for (int t = 0; t < 4; t++) {
            uint32_t h;
            h = pack_bf16(sc[2*t][0],   sc[2*t][1]);
            ph[t][0] = h;
            pl[t][0] = pack_bf16(sc[2*t][0]   - blo_f(h), sc[2*t][1]   - bhi_f(h));
            h = pack_bf16(sc[2*t][2],   sc[2*t][3]);
            ph[t][1] = h;
            pl[t][1] = pack_bf16(sc[2*t][2]   - blo_f(h), sc[2*t][3]   - bhi_f(h));
            h = pack_bf16(sc[2*t+1][0], sc[2*t+1][1]);
            ph[t][2] = h;
            pl[t][2] = pack_bf16(sc[2*t+1][0] - blo_f(h), sc[2*t+1][1] - bhi_f(h));
            h = pack_bf16(sc[2*t+1][2], sc[2*t+1][3]);
            ph[t][3] = h;
            pl[t][3] = pack_bf16(sc[2*t+1][2] - blo_f(h), sc[2*t+1][3] - bhi_f(h));
        }

        // O += P V  (3-term bf16)
        #pragma unroll
        for (int j = 0; j < 8; j++) {
            const int nrow = (8*j + gid)*AT_RS + tig*4;
            #pragma unroll
            for (int t = 0; t < 4; t++) {
                uint4 vc = *(const uint4*)&sV[nrow + t*16];
                mma_bf16(o[j], ph[t], vc.x, vc.y);
                mma_bf16(o[j], ph[t], vc.z, vc.w);
                mma_bf16(o[j], pl[t], vc.x, vc.y);
            }
        }
    }

    // Finalize: write X pre-rounded tf32, k-interleaved for the Wo GEMM
    const float inv0 = 1.0f / l0, inv1 = 1.0f / l1;
    const int b = bh >> 4, h = bh & 15;
    float* x0 = X + ((size_t)(b*SQ + row0))*DM + h*DKH;
    float* x1 = X + ((size_t)(b*SQ + row1))*DM + h*DKH;
    const int off0 = (tig < 2) ? 4*tig : 4*tig - 7;   // storage of col 2*tig
    #pragma unroll
    for (int j = 0; j < 8; j++) {
        int base = 8*j + off0;
        x0[base]     = tf32hi(o[j][0]*inv0);
        x0[base + 2] = tf32hi(o[j][1]*inv0);
        x1[base]     = tf32hi(o[j][2]*inv1);
        x1[base + 2] = tf32hi(o[j][3]*inv1);
    }
}

// ---------------------------------------------------------------------------
// Launch
// ---------------------------------------------------------------------------
extern "C" void kernel_launch(void* const* d_in, const int* in_sizes, int n_in,
                              void* d_out, int out_size)
{
    (void)in_sizes; (void)n_in; (void)out_size;
    const float* q  = (const float*)d_in[0];
    const float* k  = (const float*)d_in[1];
    const float* v  = (const float*)d_in[2];
    const float* Wq = (const float*)d_in[4];
    const float* bq = (const float*)d_in[5];
    const float* Wk = (const float*)d_in[6];
    const float* bk = (const float*)d_in[7];
    const float* Wv = (const float*)d_in[8];
    const float* bv = (const float*)d_in[9];
    const float* Wo = (const float*)d_in[10];
    const float* bo = (const float*)d_in[11];
    float* out = (float*)d_out;

    uint32_t *QhiP, *QloP, *KcP, *VcP;
    float *Xp, *qc, *kc, *vc, *Wqc, *Wkc, *Wvc, *Woc;
    cudaGetSymbolAddress((void**)&QhiP, g_Qhi);
    cudaGetSymbolAddress((void**)&QloP, g_Qlo);
    cudaGetSymbolAddress((void**)&KcP,  g_Kc);
    cudaGetSymbolAddress((void**)&VcP,  g_Vc);
    cudaGetSymbolAddress((void**)&Xp,   g_X);
    cudaGetSymbolAddress((void**)&qc,   g_qc);
    cudaGetSymbolAddress((void**)&kc,   g_kc);
    cudaGetSymbolAddress((void**)&vc,   g_vc);
    cudaGetSymbolAddress((void**)&Wqc,  g_Wqc);
    cudaGetSymbolAddress((void**)&Wkc,  g_Wkc);
    cudaGetSymbolAddress((void**)&Wvc,  g_Wvc);
    cudaGetSymbolAddress((void**)&Woc,  g_Woc);

    cudaFuncSetAttribute(gemm_tf32,
                         cudaFuncAttributeMaxDynamicSharedMemorySize, GEMM_SMEM);
    cudaFuncSetAttribute(attn_tc,
                         cudaFuncAttributeMaxDynamicSharedMemorySize, ATTN_SMEM);

    const int nA8 = NTOK*DM/8;    // 524288
    const int nW8 = DM*DM/8;      // 131072

    CvtJobs cj;
    cj.src[0] = (const float4*)q;  cj.dst[0] = (float4*)qc;  cj.n8[0] = nA8;
    cj.src[1] = (const float4*)k;  cj.dst[1] = (float4*)kc;  cj.n8[1] = nA8;
    cj.src[2] = (const float4*)v;  cj.dst[2] = (float4*)vc;  cj.n8[2] = nA8;
    cj.src[3] = (const float4*)Wq; cj.dst[3] = (float4*)Wqc; cj.n8[3] = nW8;
    cj.src[4] = (const float4*)Wk; cj.dst[4] = (float4*)Wkc; cj.n8[4] = nW8;
    cj.src[5] = (const float4*)Wv; cj.dst[5] = (float4*)Wvc; cj.n8[5] = nW8;
    cj.src[6] = (const float4*)Wo; cj.dst[6] = (float4*)Woc; cj.n8[6] = nW8;
    cvt_tf32_k<<<dim3(nA8/256, 7), 256>>>(cj);

    GemmJobs gj;
    gj.A[0] = qc; gj.W[0] = Wqc; gj.bias[0] = bq; gj.C[0] = QhiP; gj.C2[0] = QloP;   gj.mode[0] = 1;
    gj.A[1] = kc; gj.W[1] = Wkc; gj.bias[1] = bk; gj.C[1] = KcP;  gj.C2[1] = nullptr; gj.mode[1] = 4;
    gj.A[2] = vc; gj.W[2] = Wvc; gj.bias[2] = bv; gj.C[2] = VcP;  gj.C2[2] = nullptr; gj.mode[2] = 5;
    gemm_tf32<<<dim3(DM/128, NTOK/128, 3), 256, GEMM_SMEM>>>(gj);

    attn_tc<<<dim3(SQ/128, BH), 256, ATTN_SMEM>>>(QhiP, QloP, KcP, VcP, Xp);

    GemmJobs go;
    go.A[0] = Xp; go.W[0] = Woc; go.bias[0] = bo; go.C[0] = out; go.C2[0] = nullptr; go.mode[0] = 0;
    go.A[1] = go.A[2] = nullptr; go.W[1] = go.W[2] = nullptr;
    go.bias[1] = go.bias[2] = nullptr; go.C[1] = go.C[2] = nullptr;
    go.C2[1] = go.C2[2] = nullptr; go.mode[1] = go.mode[2] = 0;
    gemm_tf32<<<dim3(DM/128, NTOK/128, 1), 256, GEMM_SMEM>>>(go);
}

// round 15
// speedup vs baseline: 1.0039x; 1.0039x over previous
#include <cuda_runtime.h>
#include <cuda_bf16.h>
#include <math.h>
#include <cstdint>

// Problem constants
#define SQ    2048
#define DM    1024
#define NH    16
#define DKH   64
#define NB    2
#define NTOK  (NB*SQ)   // 4096
#define BH    (NB*NH)   // 32

// ---------------------------------------------------------------------------
// Scratch (no cudaMalloc allowed)
// ---------------------------------------------------------------------------
__device__ uint32_t g_Qhi[(size_t)BH*SQ*32];     // [B,H,S,dk-pairs]
__device__ uint32_t g_Qlo[(size_t)BH*SQ*32];
// K combined: [B,H,S][4 t][4 tig][kh0,kh1,kl0,kl1]  (64 u32 per key)
__device__ uint32_t g_Kc [(size_t)BH*SQ*64];
// V combined: [B,H,dk][32 kt][4 t][4 tig][vh0,vh1,vl0,vl1] (2048 u32 per dk)
__device__ uint32_t g_Vc [(size_t)BH*DKH*32*64];
__device__ float g_X  [(size_t)NTOK*DM];         // attn out, tf32 + k-interleaved
// pre-rounded + k-interleaved fp32(tf32) inputs / weights
__device__ float g_qc [(size_t)NTOK*DM];
__device__ float g_kc [(size_t)NTOK*DM];
__device__ float g_vc [(size_t)NTOK*DM];
__device__ float g_Wqc[(size_t)DM*DM];
__device__ float g_Wkc[(size_t)DM*DM];
__device__ float g_Wvc[(size_t)DM*DM];
__device__ float g_Woc[(size_t)DM*DM];

// ---------------------------------------------------------------------------
// Helpers
// ---------------------------------------------------------------------------
__device__ __forceinline__ uint32_t f2tf32(float f) {
    uint32_t r;
    asm("cvt.rna.tf32.f32 %0, %1;" : "=r"(r) : "f"(f));
    return r;
}
__device__ __forceinline__ float tf32hi(float f) {
    return __uint_as_float(f2tf32(f));
}
__device__ __forceinline__ float ex2(float x) {
    float y;
    asm("ex2.approx.f32 %0, %1;" : "=f"(y) : "f"(x));
    return y;
}
// pack two floats as bf16x2: low half = e, high half = o
__device__ __forceinline__ uint32_t pack_bf16(float e, float o) {
    uint32_t r;
    asm("cvt.rn.bf16x2.f32 %0, %1, %2;" : "=r"(r) : "f"(o), "f"(e));
    return r;
}
__device__ __forceinline__ float blo_f(uint32_t p) { return __uint_as_float(p << 16); }
__device__ __forceinline__ float bhi_f(uint32_t p) { return __uint_as_float(p & 0xffff0000u); }

__device__ __forceinline__ void mma_tf32(float c[4], const uint32_t a[4],
                                         const uint32_t b0, const uint32_t b1) {
    asm volatile(
        "mma.sync.aligned.m16n8k8.row.col.f32.tf32.tf32.f32 "
        "{%0,%1,%2,%3}, {%4,%5,%6,%7}, {%8,%9}, {%0,%1,%2,%3};"
        : "+f"(c[0]), "+f"(c[1]), "+f"(c[2]), "+f"(c[3])
        : "r"(a[0]), "r"(a[1]), "r"(a[2]), "r"(a[3]),
          "r"(b0), "r"(b1));
}
__device__ __forceinline__ void mma_bf16(float c[4], const uint32_t a[4],
                                         const uint32_t b0, const uint32_t b1) {
    asm volatile(
        "mma.sync.aligned.m16n8k16.row.col.f32.bf16.bf16.f32 "
        "{%0,%1,%2,%3}, {%4,%5,%6,%7}, {%8,%9}, {%0,%1,%2,%3};"
        : "+f"(c[0]), "+f"(c[1]), "+f"(c[2]), "+f"(c[3])
        : "r"(a[0]), "r"(a[1]), "r"(a[2]), "r"(a[3]),
          "r"(b0), "r"(b1));
}
__device__ __forceinline__ void cp16(uint32_t saddr, const void* g) {
    asm volatile("cp.async.cg.shared.global [%0], [%1], 16;"
                 :: "r"(saddr), "l"(g) : "memory");
}
#define CP_COMMIT() asm volatile("cp.async.commit_group;" ::: "memory")

__device__ __forceinline__ uint32_t smem_u32(const void* p) {
    uint32_t a;
    asm("{ .reg .u64 t; cvta.to.shared.u64 t, %1; cvt.u32.u64 %0, t; }"
        : "=r"(a) : "l"(p));
    return a;
}

// ---------------------------------------------------------------------------
// Merged tf32 pre-round + k-interleave pass.
// Storage order within each 8-col group: [k0,k4,k1,k5,k2,k6,k3,k7]
// (s(k) = (k&3)*2 + (k>>2)), so fragment pairs (k, k+4) are adjacent.
// ---------------------------------------------------------------------------
struct CvtJobs {
    const float4* src[7];
    float4*       dst[7];
    int           n8[7];   // number of 8-float groups
};

__global__ __launch_bounds__(256)
void cvt_tf32_k(CvtJobs jobs)
{
    const int a = blockIdx.y;
    const int i = blockIdx.x*blockDim.x + threadIdx.x;
    if (i < jobs.n8[a]) {
        float4 lo = jobs.src[a][2*i];
        float4 hi = jobs.src[a][2*i+1];
        float4 d0, d1;
        d0.x = tf32hi(lo.x); d0.y = tf32hi(hi.x);
        d0.z = tf32hi(lo.y); d0.w = tf32hi(hi.y);
        d1.x = tf32hi(lo.z); d1.y = tf32hi(hi.z);
        d1.z = tf32hi(lo.w); d1.w = tf32hi(hi.w);
        jobs.dst[a][2*i]   = d0;
        jobs.dst[a][2*i+1] = d1;
    }
}

// ---------------------------------------------------------------------------
// tf32 mma.sync GEMM, 2-stage cp.async pipeline, k-interleaved inputs,
// LDS.64 fragment loads. Merged jobs (grid.z).
// mode 0: C row-major fp32 [M,N]  (final output)
// mode 1: bf16 hi/lo packed dk-pairs -> C,C2 u32 [B,H,S,32]   (Q)
// mode 4: K combined-interleaved u32 [B,H,S,64]               (K)
// mode 5: V combined-interleaved u16 writes into u32 [B,H,dk,2048] (V)
// ---------------------------------------------------------------------------
#define BK 32
#define KP 40                          // row stride (u32), ≡8 mod 32
#define TILE_WORDS (128*KP)            // 5120
#define STAGE_W    (2*TILE_WORDS)      // 10240
#define GEMM_SMEM  (2*STAGE_W*4)       // 81920 B
#define GEMM_NT    (DM/BK)             // 32

struct GemmJobs {
    const float* A[3];
    const float* W[3];
    const float* bias[3];
    void*        C[3];
    void*        C2[3];
    int          mode[3];
};

__global__ __launch_bounds__(256, 2)
void gemm_tf32(GemmJobs jobs)
{
    extern __shared__ uint32_t sh[];
    const uint32_t smem0 = smem_u32(sh);

    const int z = blockIdx.z;
    const float* __restrict__ A    = jobs.A[z];
    const float* __restrict__ W    = jobs.W[z];
    const float* __restrict__ bias = jobs.bias[z];
    void* C  = jobs.C[z];
    void* C2 = jobs.C2[z];
    const int mode = jobs.mode[z];

    const int tid    = threadIdx.x;
    const int wid    = tid >> 5;
    const int lane   = tid & 31;
    const int gid    = lane >> 2;
    const int tig    = lane & 3;
    const int warp_m = (wid >> 2) * 64;
    const int warp_n = (wid & 3) * 32;
    const int bx     = blockIdx.x;
    const int by     = blockIdx.y;

    const float* Ab = A + (size_t)(by*128)*DM;
    const float* Wb = W + (size_t)(bx*128)*DM;

    auto prefetch = [&](int kt) {
        if (kt < GEMM_NT) {
            const uint32_t base = smem0 + (kt & 1)*(STAGE_W*4);
            #pragma unroll
            for (int t = 0; t < 8; t++) {
                int chunk = tid + t*256;            // 0..2047
                int arr   = chunk >> 10;            // 0=A, 1=B
                int w     = chunk & 1023;
                int row   = w >> 3;
                int kc4   = (w & 7) * 4;
                uint32_t so = (uint32_t)((arr*TILE_WORDS + row*KP + kc4)*4);
                const float* src = (arr ? Wb : Ab) + (size_t)row*DM + kt*BK + kc4;
                cp16(base + so, src);
            }
        }
        CP_COMMIT();
    };

    float acc[4][4][4];
    #pragma unroll
    for (int i = 0; i < 4; i++)
        #pragma unroll
        for (int j = 0; j < 4; j++)
            #pragma unroll
            for (int r = 0; r < 4; r++) acc[i][j][r] = 0.0f;

    prefetch(0);

    for (int kt = 0; kt < GEMM_NT; kt++) {
        prefetch(kt + 1);   // stage (kt+1)&1 freed by trailing barrier of prev iter
        asm volatile("cp.async.wait_group 1;" ::: "memory");
        __syncthreads();

        const uint32_t* a = sh + (kt & 1)*STAGE_W;
        const uint32_t* b = a + TILE_WORDS;

        #pragma unroll
        for (int ks = 0; ks < BK; ks += 8) {
            uint32_t af[4][4], bf[4][2];
            #pragma unroll
            for (int i = 0; i < 4; i++) {
                int r0 = warp_m + i*16 + gid;
                uint2 A0 = *(const uint2*)&a[ r0    *KP + ks + 2*tig];
                uint2 A1 = *(const uint2*)&a[(r0+8) *KP + ks + 2*tig];
                af[i][0] = A0.x; af[i][1] = A1.x;
                af[i][2] = A0.y; af[i][3] = A1.y;
            }
            #pragma unroll
            for (int j = 0; j < 4; j++) {
                int n = warp_n + j*8 + gid;
                uint2 B0 = *(const uint2*)&b[n*KP + ks + 2*tig];
                bf[j][0] = B0.x; bf[j][1] = B0.y;
            }
            #pragma unroll
            for (int i = 0; i < 4; i++)
                #pragma unroll
                for (int j = 0; j < 4; j++)
                    mma_tf32(acc[i][j], af[i], bf[j][0], bf[j][1]);
        }
        __syncthreads();   // free this stage for prefetch(kt+2)
    }

    #pragma unroll
    for (int i = 0; i < 4; i++) {
        #pragma unroll
        for (int j = 0; j < 4; j++) {
            int row0 = by*128 + warp_m + i*16 + gid;
            int row1 = row0 + 8;
            int col  = bx*128 + warp_n + j*8 + tig*2;
            float bx0 = bias[col], bx1 = bias[col+1];
            float v00 = acc[i][j][0] + bx0, v01 = acc[i][j][1] + bx1;
            float v10 = acc[i][j][2] + bx0, v11 = acc[i][j][3] + bx1;
            if (mode == 0) {
                float* Cf = (float*)C;
                *(float2*)(Cf + (size_t)row0*DM + col) = make_float2(v00, v01);
                *(float2*)(Cf + (size_t)row1*DM + col) = make_float2(v10, v11);
            } else if (mode == 1) {
                // Q: bf16 hi/lo packed dk-pairs [B,H,S,32]
                int h = col >> 6, dkp = (col & 63) >> 1;
                int b0r = row0 >> 11, s0 = row0 & (SQ-1);
                int b1r = row1 >> 11, s1 = row1 & (SQ-1);
                size_t o0 = ((size_t)(b0r*NH + h)*SQ + s0)*32 + dkp;
                size_t o1 = ((size_t)(b1r*NH + h)*SQ + s1)*32 + dkp;
                uint32_t h0 = pack_bf16(v00, v01);
                uint32_t h1 = pack_bf16(v10, v11);
                ((uint32_t*)C)[o0] = h0;
                ((uint32_t*)C)[o1] = h1;
                ((uint32_t*)C2)[o0] = pack_bf16(v00 - blo_f(h0), v01 - bhi_f(h0));
                ((uint32_t*)C2)[o1] = pack_bf16(v10 - blo_f(h1), v11 - bhi_f(h1));
            } else if (mode == 4) {
                // K combined: [B,H,S][t*16 + tig*4 + {h0,h1,l0,l1}]
                int h = col >> 6, dkp = (col & 63) >> 1;
                int t = dkp >> 3, p = dkp & 7;
                int tg = p & 3, sl = p >> 2;
                int b0r = row0 >> 11, s0 = row0 & (SQ-1);
                int b1r = row1 >> 11, s1 = row1 & (SQ-1);
                size_t o0 = ((size_t)(b0r*NH + h)*SQ + s0)*64 + t*16 + tg*4 + sl;
                size_t o1 = ((size_t)(b1r*NH + h)*SQ + s1)*64 + t*16 + tg*4 + sl;
                uint32_t h0 = pack_bf16(v00, v01);
                uint32_t h1 = pack_bf16(v10, v11);
                uint32_t* Kc = (uint32_t*)C;
                Kc[o0]     = h0;
                Kc[o0 + 2] = pack_bf16(v00 - blo_f(h0), v01 - bhi_f(h0));
                Kc[o1]     = h1;
                Kc[o1 + 2] = pack_bf16(v10 - blo_f(h1), v11 - bhi_f(h1));
            } else {
                // mode 5: V combined, u16 scatter into [B,H,dk][kt*64 + ...]
                unsigned short* Vc16 = (unsigned short*)C;
                #pragma unroll
                for (int u = 0; u < 4; u++) {
                    int s  = (u < 2) ? row0 : row1;
                    int dk = col + (u & 1);
                    float f = (u == 0) ? v00 : (u == 1) ? v01 : (u == 2) ? v10 : v11;
                    int br = s >> 11; int ss = s & (SQ-1);
                    int h  = dk >> 6; int dkl = dk & 63;
                    int kt = ss >> 6, q = ss & 63;
                    int pp = q >> 1, par = q & 1;
                    int t = pp >> 3, r = pp & 7;
                    int tg = r & 3, sl = r >> 2;
                    size_t u32idx = (((size_t)(br*NH + h)*DKH + dkl)*32 + kt)*64
                                  + t*16 + tg*4 + sl;
                    uint32_t ph = pack_bf16(f, 0.0f);
                    float fh = blo_f(ph);
                    uint32_t pl = pack_bf16(f - fh, 0.0f);
                    Vc16[u32idx*2 + par]       = (unsigned short)(ph & 0xffff);
                    Vc16[(u32idx + 2)*2 + par] = (unsigned short)(pl & 0xffff);
                }
            }
        }
    }
}

// ---------------------------------------------------------------------------
// bf16 tensor-core causal flash attention (3-term compensated splits).
// K/V smem: combined-interleaved rows, stride 80 u32 (≡16 mod 32):
// one LDS.128 yields {h0,h1,l0,l1} per (j,t) fragment group.
// ---------------------------------------------------------------------------
#define AT_RS       80                        // row stride (u32)
#define KV_ROW_W    64                        // payload u32 per row
#define ARR_W       (64*AT_RS)                // 5120 u32 per array
#define STAGE_WORDS (2*ARR_W)                 // 10240 u32 (K + V)
#define ATTN_SMEM   (2*STAGE_WORDS*4)         // 81920 B
#define COEF 0.18033688f                      // 0.125 * log2(e)

__global__ __launch_bounds__(256, 1)
void attn_tc(const uint32_t* __restrict__ Qhi, const uint32_t* __restrict__ Qlo,
             const uint32_t* __restrict__ Kc,  const uint32_t* __restrict__ Vc,
             float* __restrict__ X)
{
    extern __shared__ uint32_t sh[];
    const uint32_t smem0 = smem_u32(sh);

    const int qt   = (int)gridDim.x - 1 - (int)blockIdx.x;  // heavy tiles first
    const int bh   = blockIdx.y;
    const int tid  = threadIdx.x;
    const int wid  = tid >> 5;
    const int lane = tid & 31;
    const int gid  = lane >> 2;
    const int tig  = lane & 3;

    const int row0 = qt*128 + wid*16 + gid;
    const int row1 = row0 + 8;

    // Q fragments (pre-split bf16 pairs) in registers
    uint32_t qh[4][4], ql[4][4];
    {
        const uint32_t* q0h = Qhi + ((size_t)bh*SQ + row0)*32;
        const uint32_t* q1h = Qhi + ((size_t)bh*SQ + row1)*32;
        const uint32_t* q0l = Qlo + ((size_t)bh*SQ + row0)*32;
        const uint32_t* q1l = Qlo + ((size_t)bh*SQ + row1)*32;
        #pragma unroll
        for (int t = 0; t < 4; t++) {
            qh[t][0] = q0h[8*t + tig];     qh[t][1] = q1h[8*t + tig];
            qh[t][2] = q0h[8*t + tig + 4]; qh[t][3] = q1h[8*t + tig + 4];
            ql[t][0] = q0l[8*t + tig];     ql[t][1] = q1l[8*t + tig];
            ql[t][2] = q0l[8*t + tig + 4]; ql[t][3] = q1l[8*t + tig + 4];
        }
    }

    float o[8][4];
    #pragma unroll
    for (int j = 0; j < 8; j++)
        #pragma unroll
        for (int r = 0; r < 4; r++) o[j][r] = 0.0f;
    float m0 = -INFINITY, m1 = -INFINITY, l0 = 0.0f, l1 = 0.0f;

    const uint32_t* KcG = Kc + (size_t)bh*SQ*64;
    const uint32_t* VcG = Vc + (size_t)bh*DKH*32*64;

    auto prefetch = [&](int kt, int st) {
        const uint32_t base = smem0 + st*(STAGE_WORDS*4);
        #pragma unroll
        for (int t = 0; t < 8; t++) {
            int chunk = tid + t*256;         // 0..2047
            int arr   = chunk >> 10;         // 0=K, 1=V
            int w     = chunk & 1023;
            int row   = w >> 4;              // 0..63
            int ch    = (w & 15) * 4;        // u32 offset within payload
            uint32_t saddr = base + (uint32_t)((arr*ARR_W + row*AT_RS + ch)*4);
            const uint32_t* src = arr
                ? VcG + (size_t)row*2048 + kt*64 + ch
                : KcG + (size_t)(kt*64 + row)*64 + ch;
            cp16(saddr, src);
        }
        CP_COMMIT();
    };

    const int ktmax = 2*qt + 1;
    prefetch(0, 0);

    for (int kt = 0; kt <= ktmax; kt++) {
        const int st = kt & 1;
        asm volatile("cp.async.wait_group 0;" ::: "memory");
        __syncthreads();
        if (kt < ktmax) prefetch(kt + 1, st ^ 1);

        const uint32_t* sK = sh + st*STAGE_WORDS;
        const uint32_t* sV = sK + ARR_W;

        // S = Q K^T  (3-term bf16)
        float sc[8][4];
        #pragma unroll
        for (int j = 0; j < 8; j++)
            #pragma unroll
            for (int r = 0; r < 4; r++) sc[j][r] = 0.0f;

        #pragma unroll
        for (int j = 0; j < 8; j++) {
            const int nrow = (8*j + gid)*AT_RS + tig*4;
            #pragma unroll
            for (int t = 0; t < 4; t++) {
                uint4 kc = *(const uint4*)&sK[nrow + t*16];
                mma_bf16(sc[j], qh[t], kc.x, kc.y);
                mma_bf16(sc[j], qh[t], kc.z, kc.w);
                mma_bf16(sc[j], ql[t], kc.x, kc.y);
            }
        }

        // Causal mask
        if (kt*64 + 63 > row0) {
            #pragma unroll
            for (int j = 0; j < 8; j++) {
                int col = kt*64 + 8*j + 2*tig;
                if (col     > row0) sc[j][0] = -1e30f;
                if (col + 1 > row0) sc[j][1] = -1e30f;
                if (col     > row1) sc[j][2] = -1e30f;
                if (col + 1 > row1) sc[j][3] = -1e30f;
            }
        }

        // Online softmax
        float mx0 = -INFINITY, mx1 = -INFINITY;
        #pragma unroll
        for (int j = 0; j < 8; j++) {
            mx0 = fmaxf(mx0, fmaxf(sc[j][0], sc[j][1]));
            mx1 = fmaxf(mx1, fmaxf(sc[j][2], sc[j][3]));
        }
        #pragma unroll
        for (int off = 1; off <= 2; off <<= 1) {
            mx0 = fmaxf(mx0, __shfl_xor_sync(0xffffffffu, mx0, off));
            mx1 = fmaxf(mx1, __shfl_xor_sync(0xffffffffu, mx1, off));
        }
        float mn0 = fmaxf(m0, mx0), mn1 = fmaxf(m1, mx1);
        float a0 = ex2((m0 - mn0)*COEF), a1 = ex2((m1 - mn1)*COEF);
        m0 = mn0; m1 = mn1;

        float ls0 = 0.0f, ls1 = 0.0f;
        #pragma unroll
        for (int j = 0; j < 8; j++) {
            sc[j][0] = ex2((sc[j][0] - m0)*COEF);
            sc[j][1] = ex2((sc[j][1] - m0)*COEF);
            sc[j][2] = ex2((sc[j][2] - m1)*COEF);
            sc[j][3] = ex2((sc[j][3] - m1)*COEF);
            ls0 += sc[j][0] + sc[j][1];
            ls1 += sc[j][2] + sc[j][3];
        }
        #pragma unroll
        for (int off = 1; off <= 2; off <<= 1) {
            ls0 += __shfl_xor_sync(0xffffffffu, ls0, off);
            ls1 += __shfl_xor_sync(0xffffffffu, ls1, off);
        }
        l0 = l0*a0 + ls0;
        l1 = l1*a1 + ls1;
        #pragma unroll
        for (int j = 0; j < 8; j++) {
            o[j][0] *= a0; o[j][1] *= a0;
            o[j][2] *= a1; o[j][3] *= a1;
        }

        // P: accumulator pairs -> k16 A fragments via bf16x2 packing (no shfl)
        uint32_t ph[4][4], pl[4][4];
        #pragma unroll
        for (int t = 0; t < 4; t++) {
            uint32_t h;
            h = pack_bf16(sc[2*t][0],   sc[2*t][1]);
            ph[t][0] = h;
            pl[t][0] = pack_bf16(sc[2*t][0]   - blo_f(h), sc[2*t][1]   - bhi_f(h));
            h = pack_bf16(sc[2*t][2],   sc[2*t][3]);
            ph[t][1] = h;
            pl[t][1] = pack_bf16(sc[2*t][2]   - blo_f(h), sc[2*t][3]   - bhi_f(h));
            h = pack_bf16(sc[2*t+1][0], sc[2*t+1][1]);
            ph[t][2] = h;
            pl[t][2] = pack_bf16(sc[2*t+1][0] - blo_f(h), sc[2*t+1][1] - bhi_f(h));
            h = pack_bf16(sc[2*t+1][2], sc[2*t+1][3]);
            ph[t][3] = h;
            pl[t][3] = pack_bf16(sc[2*t+1][2] - blo_f(h), sc[2*t+1][3] - bhi_f(h));
        }

        // O += P V  (3-term bf16)
        #pragma unroll
        for (int j = 0; j < 8; j++) {
            const int nrow = (8*j + gid)*AT_RS + tig*4;
            #pragma unroll
            for (int t = 0; t < 4; t++) {
                uint4 vc = *(const uint4*)&sV[nrow + t*16];
                mma_bf16(o[j], ph[t], vc.x, vc.y);
                mma_bf16(o[j], ph[t], vc.z, vc.w);
                mma_bf16(o[j], pl[t], vc.x, vc.y);
            }
        }
    }

    // Finalize: write X pre-rounded tf32, k-interleaved for the Wo GEMM
    const float inv0 = 1.0f / l0, inv1 = 1.0f / l1;
    const int b = bh >> 4, h = bh & 15;
    float* x0 = X + ((size_t)(b*SQ + row0))*DM + h*DKH;
    float* x1 = X + ((size_t)(b*SQ + row1))*DM + h*DKH;
    const int off0 = (tig < 2) ? 4*tig : 4*tig - 7;   // storage of col 2*tig
    #pragma unroll
    for (int j = 0; j < 8; j++) {
        int base = 8*j + off0;
        x0[base]     = tf32hi(o[j][0]*inv0);
        x0[base + 2] = tf32hi(o[j][1]*inv0);
        x1[base]     = tf32hi(o[j][2]*inv1);
        x1[base + 2] = tf32hi(o[j][3]*inv1);
    }
}

// ---------------------------------------------------------------------------
// Launch
// ---------------------------------------------------------------------------
extern "C" void kernel_launch(void* const* d_in, const int* in_sizes, int n_in,
                              void* d_out, int out_size)
{
    (void)in_sizes; (void)n_in; (void)out_size;
    const float* q  = (const float*)d_in[0];
    const float* k  = (const float*)d_in[1];
    const float* v  = (const float*)d_in[2];
    const float* Wq = (const float*)d_in[4];
    const float* bq = (const float*)d_in[5];
    const float* Wk = (const float*)d_in[6];
    const float* bk = (const float*)d_in[7];
    const float* Wv = (const float*)d_in[8];
    const float* bv = (const float*)d_in[9];
    const float* Wo = (const float*)d_in[10];
    const float* bo = (const float*)d_in[11];
    float* out = (float*)d_out;

    uint32_t *QhiP, *QloP, *KcP, *VcP;
    float *Xp, *qc, *kc, *vc, *Wqc, *Wkc, *Wvc, *Woc;
    cudaGetSymbolAddress((void**)&QhiP, g_Qhi);
    cudaGetSymbolAddress((void**)&QloP, g_Qlo);
    cudaGetSymbolAddress((void**)&KcP,  g_Kc);
    cudaGetSymbolAddress((void**)&VcP,  g_Vc);
    cudaGetSymbolAddress((void**)&Xp,   g_X);
    cudaGetSymbolAddress((void**)&qc,   g_qc);
    cudaGetSymbolAddress((void**)&kc,   g_kc);
    cudaGetSymbolAddress((void**)&vc,   g_vc);
    cudaGetSymbolAddress((void**)&Wqc,  g_Wqc);
    cudaGetSymbolAddress((void**)&Wkc,  g_Wkc);
    cudaGetSymbolAddress((void**)&Wvc,  g_Wvc);
    cudaGetSymbolAddress((void**)&Woc,  g_Woc);

    cudaFuncSetAttribute(gemm_tf32,
                         cudaFuncAttributeMaxDynamicSharedMemorySize, GEMM_SMEM);
    cudaFuncSetAttribute(attn_tc,
                         cudaFuncAttributeMaxDynamicSharedMemorySize, ATTN_SMEM);

    const int nA8 = NTOK*DM/8;    // 524288
    const int nW8 = DM*DM/8;      // 131072

    CvtJobs cj;
    cj.src[0] = (const float4*)q;  cj.dst[0] = (float4*)qc;  cj.n8[0] = nA8;
    cj.src[1] = (const float4*)k;  cj.dst[1] = (float4*)kc;  cj.n8[1] = nA8;
    cj.src[2] = (const float4*)v;  cj.dst[2] = (float4*)vc;  cj.n8[2] = nA8;
    cj.src[3] = (const float4*)Wq; cj.dst[3] = (float4*)Wqc; cj.n8[3] = nW8;
    cj.src[4] = (const float4*)Wk; cj.dst[4] = (float4*)Wkc; cj.n8[4] = nW8;
    cj.src[5] = (const float4*)Wv; cj.dst[5] = (float4*)Wvc; cj.n8[5] = nW8;
    cj.src[6] = (const float4*)Wo; cj.dst[6] = (float4*)Woc; cj.n8[6] = nW8;
    cvt_tf32_k<<<dim3(nA8/256, 7), 256>>>(cj);

    GemmJobs gj;
    gj.A[0] = qc; gj.W[0] = Wqc; gj.bias[0] = bq; gj.C[0] = QhiP; gj.C2[0] = QloP;   gj.mode[0] = 1;
    gj.A[1] = kc; gj.W[1] = Wkc; gj.bias[1] = bk; gj.C[1] = KcP;  gj.C2[1] = nullptr; gj.mode[1] = 4;
    gj.A[2] = vc; gj.W[2] = Wvc; gj.bias[2] = bv; gj.C[2] = VcP;  gj.C2[2] = nullptr; gj.mode[2] = 5;
    gemm_tf32<<<dim3(DM/128, NTOK/128, 3), 256, GEMM_SMEM>>>(gj);

    attn_tc<<<dim3(SQ/128, BH), 256, ATTN_SMEM>>>(QhiP, QloP, KcP, VcP, Xp);

    GemmJobs go;
    go.A[0] = Xp; go.W[0] = Woc; go.bias[0] = bo; go.C[0] = out; go.C2[0] = nullptr; go.mode[0] = 0;
    go.A[1] = go.A[2] = nullptr; go.W[1] = go.W[2] = nullptr;
    go.bias[1] = go.bias[2] = nullptr; go.C[1] = go.C[2] = nullptr;
    go.C2[1] = go.C2[2] = nullptr; go.mode[1] = go.mode[2] = 0;
    gemm_tf32<<<dim3(DM/128, NTOK/128, 1), 256, GEMM_SMEM>>>(go);
}